// round 13
// baseline (speedup 1.0000x reference)
#include <cuda_runtime.h>
#include <cuda_bf16.h>
#include <math.h>
#include <stdint.h>

#define M_ROWS 8192
#define C_COLS 4096
#define D_DIM  768

#define BM 128
#define BN 128
#define BKB 192                    // K bytes (int8 elems) per chunk
#define NTH 256
#define NKC (D_DIM / BKB)          // 4
#define NKS (BKB / 32)             // 6 k32 steps per chunk
#define NMT (M_ROWS / BM)          // 64
#define NCT (C_COLS / BN)          // 32

#define LDA  (BKB + 16)            // 208-byte rows: bank phase (13r+c)%8 distinct -> conflict-free
#define TILE_BYTES (BM * LDA)              // 26624
#define STAGE_BYTES (2 * TILE_BYTES)       // 53248 (A then B)
#define NSTAGE 2
#define SMEM_BYTES (NSTAGE * STAGE_BYTES)  // 106496

__device__ __align__(16) char g_A[M_ROWS * D_DIM];   // int8 quantized
__device__ __align__(16) char g_B[C_COLS * D_DIM];
__device__ float g_at[M_ROWS];     // time components
__device__ float g_bt[C_COLS];
__device__ float g_sa[M_ROWS];     // dequant scales (absmax/127)
__device__ float g_sb[C_COLS];
__device__ float g_p1[NCT * M_ROWS], g_p2[NCT * M_ROWS], g_pp[NCT * M_ROWS];

__device__ __forceinline__ uint32_t smem_u32(const void* p) {
    uint32_t a;
    asm("{ .reg .u64 t; cvta.to.shared.u64 t, %1; cvt.u32.u64 %0, t; }" : "=r"(a) : "l"(p));
    return a;
}
__device__ __forceinline__ void cp16(uint32_t dst, const void* src) {
    asm volatile("cp.async.cg.shared.global [%0], [%1], 16;" :: "r"(dst), "l"(src));
}
__device__ __forceinline__ void cp_commit() { asm volatile("cp.async.commit_group;"); }
template<int N> __device__ __forceinline__ void cp_wait() {
    asm volatile("cp.async.wait_group %0;" :: "n"(N));
}
__device__ __forceinline__ void ldsm4(uint32_t* r, uint32_t addr) {
    asm volatile("ldmatrix.sync.aligned.m8n8.x4.shared.b16 {%0,%1,%2,%3}, [%4];"
                 : "=r"(r[0]), "=r"(r[1]), "=r"(r[2]), "=r"(r[3]) : "r"(addr));
}
__device__ __forceinline__ void imma16832(int* c, const uint32_t* a, uint32_t b0, uint32_t b1) {
    asm volatile(
        "mma.sync.aligned.m16n8k32.row.col.s32.s8.s8.s32 "
        "{%0,%1,%2,%3}, {%4,%5,%6,%7}, {%8,%9}, {%0,%1,%2,%3};\n"
        : "+r"(c[0]), "+r"(c[1]), "+r"(c[2]), "+r"(c[3])
        : "r"(a[0]), "r"(a[1]), "r"(a[2]), "r"(a[3]), "r"(b0), "r"(b1));
}

// ---------------------------------------------------------------------------
// Prep: scale -> exp_map0 -> per-row absmax int8 quantization + fp32 time.
// Warp-per-row; warp-only reductions.
// ---------------------------------------------------------------------------
__global__ void __launch_bounds__(256)
prep_kernel(const float* __restrict__ text,
            const float* __restrict__ label,
            const float* __restrict__ curv_log,
            const float* __restrict__ ta_log,
            const float* __restrict__ la_log) {
    const int gw = blockIdx.x * 8 + (threadIdx.x >> 5);
    const int lane = threadIdx.x & 31;
    const int which = gw >= M_ROWS;
    const int row = which ? gw - M_ROWS : gw;
    const float alpha = expf(which ? la_log[0] : ta_log[0]);
    const float curv  = expf(curv_log[0]);
    const float4* xr = (const float4*)((which ? label : text) + (size_t)row * D_DIM);

    float4 v[6];
    float ss = 0.0f, amax = 0.0f;
    #pragma unroll
    for (int j = 0; j < 6; ++j) {
        float4 t = xr[j * 32 + lane];
        t.x *= alpha; t.y *= alpha; t.z *= alpha; t.w *= alpha;
        ss += t.x * t.x + t.y * t.y + t.z * t.z + t.w * t.w;
        amax = fmaxf(amax, fmaxf(fmaxf(fabsf(t.x), fabsf(t.y)), fmaxf(fabsf(t.z), fabsf(t.w))));
        v[j] = t;
    }
    #pragma unroll
    for (int o = 16; o > 0; o >>= 1) {
        ss += __shfl_xor_sync(0xffffffffu, ss, o);
        amax = fmaxf(amax, __shfl_xor_sync(0xffffffffu, amax, o));
    }

    const float rc = sqrtf(curv) * sqrtf(ss);
    const float sf = sinhf(rc) / fmaxf(rc, 1e-8f);

    const float qmax = fmaxf(sf * amax, 1e-20f);
    const float inv_scale = 127.0f / qmax;

    uint32_t* orow = (uint32_t*)((which ? g_B : g_A) + (size_t)row * D_DIM);
    #pragma unroll
    for (int j = 0; j < 6; ++j) {
        int q0 = __float2int_rn(sf * v[j].x * inv_scale);
        int q1 = __float2int_rn(sf * v[j].y * inv_scale);
        int q2 = __float2int_rn(sf * v[j].z * inv_scale);
        int q3 = __float2int_rn(sf * v[j].w * inv_scale);
        q0 = max(-127, min(127, q0)); q1 = max(-127, min(127, q1));
        q2 = max(-127, min(127, q2)); q3 = max(-127, min(127, q3));
        orow[j * 32 + lane] = (uint32_t)(q0 & 0xFF) | ((uint32_t)(q1 & 0xFF) << 8) |
                              ((uint32_t)(q2 & 0xFF) << 16) | ((uint32_t)(q3 & 0xFF) << 24);
    }
    if (lane == 0) {
        (which ? g_bt : g_at)[row] = sqrtf(1.0f / curv + sf * sf * ss);
        (which ? g_sb : g_sa)[row] = qmax * (1.0f / 127.0f);
    }
}

// ---------------------------------------------------------------------------
// Stage loader: A[128 x 192B] + B[128 x 192B] int8 into ring slot.
// thread -> row tid>>1, chunks (tid&1)*6 + j (12 x 16B chunks per row).
// ---------------------------------------------------------------------------
__device__ __forceinline__ void load_stage(char* smem, int slot, int mt, int ct,
                                           int kc, int tid) {
    char* sb = smem + slot * STAGE_BYTES;
    const int r  = tid >> 1;
    const int c0 = (tid & 1) * 6;
    const char* Ag = g_A + ((size_t)mt * BM + r) * D_DIM + kc * BKB;
    const char* Bg = g_B + ((size_t)ct * BN + r) * D_DIM + kc * BKB;
    char* dA = sb + r * LDA;
    char* dB = sb + TILE_BYTES + r * LDA;
    #pragma unroll
    for (int j = 0; j < 6; ++j) {
        const int ch = (c0 + j) * 16;
        cp16(smem_u32(dA + ch), Ag + ch);
        cp16(smem_u32(dB + ch), Bg + ch);
    }
}

// ---------------------------------------------------------------------------
// Main int8 GEMM: grid = 2048 CTAs, 256 thr, 2 CTAs/SM, warp tile 32x64.
// 2-stage BKB=192 double buffer (4 chunks/tile), one barrier per chunk.
// Epilogue: branchless top-2 on v' = (xt/sa)*yt - f*sb (rank-preserving);
// scale restored at partial write.
// ---------------------------------------------------------------------------
__global__ void __launch_bounds__(NTH, 2)
clloss_main(const int* __restrict__ target) {
    extern __shared__ char smem[];
    const int tid  = threadIdx.x;
    const int warp = tid >> 5;
    const int lane = tid & 31;
    const int g    = lane >> 2;
    const int q    = lane & 3;
    const int wm   = warp >> 1;     // 0..3
    const int wn   = warp & 1;      // 0..1
    const int ct   = blockIdx.x & (NCT - 1);
    const int mt   = blockIdx.x >> 5;

    load_stage(smem, 0, mt, ct, 0, tid); cp_commit();

    const uint32_t s0 = smem_u32(smem);
    const uint32_t aOff = (uint32_t)((wm * 32 + (lane & 15)) * LDA + (lane >> 4) * 16);
    const int bn = (lane & 7) + ((lane & 16) >> 1);
    const uint32_t bOff = (uint32_t)TILE_BYTES +
                          (uint32_t)((wn * 64 + bn) * LDA + ((lane >> 3) & 1) * 16);

    int acc[2][8][4];
    #pragma unroll
    for (int mi = 0; mi < 2; ++mi)
        #pragma unroll
        for (int ni = 0; ni < 8; ++ni)
            #pragma unroll
            for (int r = 0; r < 4; ++r) acc[mi][ni][r] = 0;

    #pragma unroll 1
    for (int kc = 0; kc < NKC; ++kc) {
        cp_wait<0>();
        __syncthreads();               // stage kc ready, other slot's reads done
        if (kc + 1 < NKC) {
            load_stage(smem, (kc + 1) & 1, mt, ct, kc + 1, tid);
            cp_commit();
        }
        const uint32_t sb = s0 + (uint32_t)((kc & 1) * STAGE_BYTES);

        // Preload B fragments for ks=0 (double-buffered across ks).
        uint32_t b[2][4][4];
        #pragma unroll
        for (int nb = 0; nb < 4; ++nb)
            ldsm4(b[0][nb], sb + bOff + nb * 16 * LDA);

        #pragma unroll
        for (int ks = 0; ks < NKS; ++ks) {   // 6 x k32 per 192-byte chunk
            const int cur = ks & 1, nxt = cur ^ 1;
            uint32_t a[2][4];
            ldsm4(a[0], sb + aOff + ks * 32);
            ldsm4(a[1], sb + aOff + ks * 32 + 16 * LDA);
            if (ks < NKS - 1) {
                #pragma unroll
                for (int nb = 0; nb < 4; ++nb)
                    ldsm4(b[nxt][nb], sb + bOff + (ks + 1) * 32 + nb * 16 * LDA);
            }
            #pragma unroll
            for (int mi = 0; mi < 2; ++mi)
                #pragma unroll
                for (int ni = 0; ni < 8; ++ni)
                    imma16832(acc[mi][ni], a[mi],
                              b[cur][ni >> 1][(ni & 1) * 2], b[cur][ni >> 1][(ni & 1) * 2 + 1]);
        }
    }

    // Epilogue: v' = xs*yt - f*sb where xs = xt/sa (rank-preserving per row).
    float xs[4]; int tg[4];
    #pragma unroll
    for (int i = 0; i < 4; ++i) {
        const int rg = mt * BM + wm * 32 + (i >> 1) * 16 + (i & 1) * 8 + g;
        xs[i] = __fdividef(g_at[rg], g_sa[rg]);
        tg[i] = target[rg];
    }
    const float FINF = __int_as_float(0x7f800000);
    float m1[4], m2[4], vp[4];
    #pragma unroll
    for (int i = 0; i < 4; ++i) { m1[i] = FINF; m2[i] = FINF; vp[i] = FINF; }

    #pragma unroll
    for (int ni = 0; ni < 8; ++ni) {
        const int cg  = ct * BN + wn * 64 + ni * 8 + 2 * q;   // even -> float2-aligned
        const float2 yt2 = *(const float2*)&g_bt[cg];
        const float2 sb2 = *(const float2*)&g_sb[cg];
        #pragma unroll
        for (int mi = 0; mi < 2; ++mi) {
            #pragma unroll
            for (int h = 0; h < 2; ++h) {
                const int i = mi * 2 + h;
                float va = fmaf(-(float)acc[mi][ni][h * 2 + 0], sb2.x, xs[i] * yt2.x);
                float vb = fmaf(-(float)acc[mi][ni][h * 2 + 1], sb2.y, xs[i] * yt2.y);
                const bool pa = (cg == tg[i]);
                const bool pb = (cg + 1 == tg[i]);
                vp[i] = pa ? va : vp[i];
                va    = pa ? FINF : va;
                vp[i] = pb ? vb : vp[i];
                vb    = pb ? FINF : vb;
                float mxa = fmaxf(m1[i], va);
                m1[i] = fminf(m1[i], va);
                m2[i] = fminf(m2[i], mxa);
                float mxb = fmaxf(m1[i], vb);
                m1[i] = fminf(m1[i], vb);
                m2[i] = fminf(m2[i], mxb);
            }
        }
    }

    // Quad merge (q lanes share rows; same row -> same sa -> order preserved)
    #pragma unroll
    for (int i = 0; i < 4; ++i) {
        #pragma unroll
        for (int off = 1; off <= 2; off <<= 1) {
            float o1 = __shfl_xor_sync(0xffffffffu, m1[i], off);
            float o2 = __shfl_xor_sync(0xffffffffu, m2[i], off);
            float op = __shfl_xor_sync(0xffffffffu, vp[i], off);
            float n1 = fminf(m1[i], o1);
            float n2 = fminf(fmaxf(m1[i], o1), fminf(m2[i], o2));
            m1[i] = n1; m2[i] = n2;
            vp[i] = fminf(vp[i], op);
        }
    }

    // wn merge via smem (reuses stage area — protected by mainloop barrier).
    float* r1 = (float*)smem;
    float* r2 = r1 + 2 * BM;
    float* rp = r2 + 2 * BM;
    if (q == 0) {
        #pragma unroll
        for (int i = 0; i < 4; ++i) {
            const int rl = wm * 32 + (i >> 1) * 16 + (i & 1) * 8 + g;
            r1[wn * BM + rl] = m1[i];
            r2[wn * BM + rl] = m2[i];
            rp[wn * BM + rl] = vp[i];
        }
    }
    __syncthreads();
    if (tid < BM) {
        const float saw = g_sa[mt * BM + tid];    // restore per-row scale
        const float a1 = r1[tid], b1 = r1[BM + tid];
        const float a2 = r2[tid], b2 = r2[BM + tid];
        const float n1 = fminf(a1, b1);
        const float n2 = fminf(fmaxf(a1, b1), fminf(a2, b2));
        const int gi = ct * M_ROWS + mt * BM + tid;
        g_p1[gi] = n1 * saw;
        g_p2[gi] = n2 * saw;
        g_pp[gi] = fminf(rp[tid], rp[BM + tid]) * saw;
    }
}

// ---------------------------------------------------------------------------
// Merge partials across 32 ct-tiles + per-sample loss.
// ---------------------------------------------------------------------------
__global__ void merge_loss(const float* __restrict__ curv_log, float* __restrict__ out) {
    const int r = blockIdx.x * 256 + threadIdx.x;
    float a1 = g_p1[r], a2 = g_p2[r], ap = g_pp[r];
    #pragma unroll 4
    for (int ct = 1; ct < NCT; ++ct) {
        const float b1 = g_p1[ct * M_ROWS + r];
        const float b2 = g_p2[ct * M_ROWS + r];
        const float n1 = fminf(a1, b1);
        a2 = fminf(fmaxf(a1, b1), fminf(a2, b2));
        a1 = n1;
        ap = fminf(ap, g_pp[ct * M_ROWS + r]);
    }
    const float curv = expf(curv_log[0]);
    const float sc = sqrtf(curv);
    const float dp = acoshf(fmaxf(curv * ap, 1.0f)) / sc;
    const float d1 = acoshf(fmaxf(curv * a1, 1.0f)) / sc;
    const float d2 = acoshf(fmaxf(curv * a2, 1.0f)) / sc;
    const float s0 = -dp, s1 = -d1, s2 = -d2;
    const float mx = fmaxf(s0, fmaxf(s1, s2));
    out[r] = mx + logf(expf(s0 - mx) + expf(s1 - mx) + expf(s2 - mx)) - s0;
}

extern "C" void kernel_launch(void* const* d_in, const int* in_sizes, int n_in,
                              void* d_out, int out_size) {
    const float* text     = (const float*)d_in[0];
    const float* label    = (const float*)d_in[1];
    const int*   tgt      = (const int*)d_in[2];
    const float* curv_log = (const float*)d_in[3];
    const float* ta_log   = (const float*)d_in[4];
    const float* la_log   = (const float*)d_in[5];
    float* out = (float*)d_out;

    cudaFuncSetAttribute(clloss_main, cudaFuncAttributeMaxDynamicSharedMemorySize, SMEM_BYTES);

    prep_kernel<<<(M_ROWS + C_COLS) / 8, 256>>>(text, label, curv_log, ta_log, la_log);
    clloss_main<<<NMT * NCT, NTH, SMEM_BYTES>>>(tgt);
    merge_loss<<<M_ROWS / 256, 256>>>(curv_log, out);
}

// round 14
// speedup vs baseline: 1.4592x; 1.4592x over previous
#include <cuda_runtime.h>
#include <cuda_bf16.h>
#include <math.h>
#include <stdint.h>

#define M_ROWS 8192
#define C_COLS 4096
#define D_DIM  768

#define BM 128
#define BN 128
#define BKB 128                    // K bytes (int8 elems) per chunk
#define NTH 256
#define NKC (D_DIM / BKB)          // 6
#define NMT (M_ROWS / BM)          // 64
#define NCT (C_COLS / BN)          // 32

#define LDA  (BKB + 16)            // 144-byte rows: conflict-free ldmatrix
#define TILE_BYTES (BM * LDA)              // 18432
#define STAGE_BYTES (2 * TILE_BYTES)       // 36864 (A then B)
#define NSTAGE 3
#define SMEM_BYTES (NSTAGE * STAGE_BYTES)  // 110592

__device__ __align__(16) char g_A[M_ROWS * D_DIM];   // int8 quantized
__device__ __align__(16) char g_B[C_COLS * D_DIM];
__device__ float g_at[M_ROWS];     // time components
__device__ float g_bt[C_COLS];
__device__ float g_sa[M_ROWS];     // dequant scales (absmax/127)
__device__ float g_sb[C_COLS];
__device__ float g_p1[NCT * M_ROWS], g_p2[NCT * M_ROWS], g_pp[NCT * M_ROWS];

__device__ __forceinline__ uint32_t smem_u32(const void* p) {
    uint32_t a;
    asm("{ .reg .u64 t; cvta.to.shared.u64 t, %1; cvt.u32.u64 %0, t; }" : "=r"(a) : "l"(p));
    return a;
}
__device__ __forceinline__ void cp16(uint32_t dst, const void* src) {
    asm volatile("cp.async.cg.shared.global [%0], [%1], 16;" :: "r"(dst), "l"(src));
}
__device__ __forceinline__ void cp_commit() { asm volatile("cp.async.commit_group;"); }
template<int N> __device__ __forceinline__ void cp_wait() {
    asm volatile("cp.async.wait_group %0;" :: "n"(N));
}
__device__ __forceinline__ void ldsm4(uint32_t* r, uint32_t addr) {
    asm volatile("ldmatrix.sync.aligned.m8n8.x4.shared.b16 {%0,%1,%2,%3}, [%4];"
                 : "=r"(r[0]), "=r"(r[1]), "=r"(r[2]), "=r"(r[3]) : "r"(addr));
}
__device__ __forceinline__ void imma16832(int* c, const uint32_t* a, uint32_t b0, uint32_t b1) {
    asm volatile(
        "mma.sync.aligned.m16n8k32.row.col.s32.s8.s8.s32 "
        "{%0,%1,%2,%3}, {%4,%5,%6,%7}, {%8,%9}, {%0,%1,%2,%3};\n"
        : "+r"(c[0]), "+r"(c[1]), "+r"(c[2]), "+r"(c[3])
        : "r"(a[0]), "r"(a[1]), "r"(a[2]), "r"(a[3]), "r"(b0), "r"(b1));
}

// ---------------------------------------------------------------------------
// Prep: scale -> exp_map0 -> per-row absmax int8 quantization + fp32 time.
// Warp-per-row; warp-only reductions.
// ---------------------------------------------------------------------------
__global__ void __launch_bounds__(256)
prep_kernel(const float* __restrict__ text,
            const float* __restrict__ label,
            const float* __restrict__ curv_log,
            const float* __restrict__ ta_log,
            const float* __restrict__ la_log) {
    const int gw = blockIdx.x * 8 + (threadIdx.x >> 5);
    const int lane = threadIdx.x & 31;
    const int which = gw >= M_ROWS;
    const int row = which ? gw - M_ROWS : gw;
    const float alpha = expf(which ? la_log[0] : ta_log[0]);
    const float curv  = expf(curv_log[0]);
    const float4* xr = (const float4*)((which ? label : text) + (size_t)row * D_DIM);

    float4 v[6];
    float ss = 0.0f, amax = 0.0f;
    #pragma unroll
    for (int j = 0; j < 6; ++j) {
        float4 t = xr[j * 32 + lane];
        t.x *= alpha; t.y *= alpha; t.z *= alpha; t.w *= alpha;
        ss += t.x * t.x + t.y * t.y + t.z * t.z + t.w * t.w;
        amax = fmaxf(amax, fmaxf(fmaxf(fabsf(t.x), fabsf(t.y)), fmaxf(fabsf(t.z), fabsf(t.w))));
        v[j] = t;
    }
    #pragma unroll
    for (int o = 16; o > 0; o >>= 1) {
        ss += __shfl_xor_sync(0xffffffffu, ss, o);
        amax = fmaxf(amax, __shfl_xor_sync(0xffffffffu, amax, o));
    }

    const float rc = sqrtf(curv) * sqrtf(ss);
    const float sf = sinhf(rc) / fmaxf(rc, 1e-8f);

    const float qmax = fmaxf(sf * amax, 1e-20f);
    const float inv_scale = 127.0f / qmax;

    uint32_t* orow = (uint32_t*)((which ? g_B : g_A) + (size_t)row * D_DIM);
    #pragma unroll
    for (int j = 0; j < 6; ++j) {
        int q0 = __float2int_rn(sf * v[j].x * inv_scale);
        int q1 = __float2int_rn(sf * v[j].y * inv_scale);
        int q2 = __float2int_rn(sf * v[j].z * inv_scale);
        int q3 = __float2int_rn(sf * v[j].w * inv_scale);
        q0 = max(-127, min(127, q0)); q1 = max(-127, min(127, q1));
        q2 = max(-127, min(127, q2)); q3 = max(-127, min(127, q3));
        orow[j * 32 + lane] = (uint32_t)(q0 & 0xFF) | ((uint32_t)(q1 & 0xFF) << 8) |
                              ((uint32_t)(q2 & 0xFF) << 16) | ((uint32_t)(q3 & 0xFF) << 24);
    }
    if (lane == 0) {
        (which ? g_bt : g_at)[row] = sqrtf(1.0f / curv + sf * sf * ss);
        (which ? g_sb : g_sa)[row] = qmax * (1.0f / 127.0f);
    }
}

// ---------------------------------------------------------------------------
// Stage loader: A[128 x 128B] + B[128 x 128B] int8 into ring slot.
// 2048 cp16 / 256 threads.
// ---------------------------------------------------------------------------
__device__ __forceinline__ void load_stage(char* smem, int slot, int mt, int ct,
                                           int kc, int tid) {
    char* sb = smem + slot * STAGE_BYTES;
    const char* Ag = g_A + ((size_t)mt * BM) * D_DIM + kc * BKB;
    const char* Bg = g_B + ((size_t)ct * BN) * D_DIM + kc * BKB;
    #pragma unroll
    for (int t = 0; t < 4; ++t) {
        int i = tid + t * NTH;              // 0..1023
        int r = i >> 3, ch = (i & 7) * 16;
        cp16(smem_u32(sb + r * LDA + ch), Ag + (size_t)r * D_DIM + ch);
        cp16(smem_u32(sb + TILE_BYTES + r * LDA + ch), Bg + (size_t)r * D_DIM + ch);
    }
}

// ---------------------------------------------------------------------------
// Main int8 GEMM: grid = 2048 CTAs, 256 thr, 2 CTAs/SM, warp tile 32x64.
// 3-stage BKB=128 ring, distance-2 prefetch, one barrier per chunk
// (R12 structure). Epilogue: branchless top-2 on v' = (xt/sa)*yt - f*sb
// (rank-preserving); scale restored at partial write.
// ---------------------------------------------------------------------------
__global__ void __launch_bounds__(NTH, 2)
clloss_main(const int* __restrict__ target) {
    extern __shared__ char smem[];
    const int tid  = threadIdx.x;
    const int warp = tid >> 5;
    const int lane = tid & 31;
    const int g    = lane >> 2;
    const int q    = lane & 3;
    const int wm   = warp >> 1;     // 0..3
    const int wn   = warp & 1;      // 0..1
    const int ct   = blockIdx.x & (NCT - 1);
    const int mt   = blockIdx.x >> 5;

    load_stage(smem, 0, mt, ct, 0, tid); cp_commit();
    load_stage(smem, 1, mt, ct, 1, tid); cp_commit();

    const uint32_t s0 = smem_u32(smem);
    const uint32_t aOff = (uint32_t)((wm * 32 + (lane & 15)) * LDA + (lane >> 4) * 16);
    const int bn = (lane & 7) + ((lane & 16) >> 1);
    const uint32_t bOff = (uint32_t)TILE_BYTES +
                          (uint32_t)((wn * 64 + bn) * LDA + ((lane >> 3) & 1) * 16);

    int acc[2][8][4];
    #pragma unroll
    for (int mi = 0; mi < 2; ++mi)
        #pragma unroll
        for (int ni = 0; ni < 8; ++ni)
            #pragma unroll
            for (int r = 0; r < 4; ++r) acc[mi][ni][r] = 0;

    #pragma unroll 1
    for (int kc = 0; kc < NKC; ++kc) {
        if (kc < NKC - 1) cp_wait<1>(); else cp_wait<0>();
        __syncthreads();               // stage kc ready, slot (kc+2)%3 free
        const uint32_t sb = s0 + (uint32_t)((kc % 3) * STAGE_BYTES);

        // Preload B fragments for ks=0 (double-buffered across ks).
        uint32_t b[2][4][4];
        #pragma unroll
        for (int nb = 0; nb < 4; ++nb)
            ldsm4(b[0][nb], sb + bOff + nb * 16 * LDA);

        if (kc + 2 < NKC) {
            load_stage(smem, (kc + 2) % 3, mt, ct, kc + 2, tid);
            cp_commit();
        }

        #pragma unroll
        for (int ks = 0; ks < 4; ++ks) {   // 4 x k32 per 128-byte chunk
            const int cur = ks & 1, nxt = cur ^ 1;
            uint32_t a[2][4];
            ldsm4(a[0], sb + aOff + ks * 32);
            ldsm4(a[1], sb + aOff + ks * 32 + 16 * LDA);
            if (ks < 3) {
                #pragma unroll
                for (int nb = 0; nb < 4; ++nb)
                    ldsm4(b[nxt][nb], sb + bOff + (ks + 1) * 32 + nb * 16 * LDA);
            }
            #pragma unroll
            for (int mi = 0; mi < 2; ++mi)
                #pragma unroll
                for (int ni = 0; ni < 8; ++ni)
                    imma16832(acc[mi][ni], a[mi],
                              b[cur][ni >> 1][(ni & 1) * 2], b[cur][ni >> 1][(ni & 1) * 2 + 1]);
        }
    }

    // Epilogue: v' = xs*yt - f*sb where xs = xt/sa (rank-preserving per row).
    float xs[4]; int tg[4];
    #pragma unroll
    for (int i = 0; i < 4; ++i) {
        const int rg = mt * BM + wm * 32 + (i >> 1) * 16 + (i & 1) * 8 + g;
        xs[i] = __fdividef(g_at[rg], g_sa[rg]);
        tg[i] = target[rg];
    }
    const float FINF = __int_as_float(0x7f800000);
    float m1[4], m2[4], vp[4];
    #pragma unroll
    for (int i = 0; i < 4; ++i) { m1[i] = FINF; m2[i] = FINF; vp[i] = FINF; }

    #pragma unroll
    for (int ni = 0; ni < 8; ++ni) {
        const int cg  = ct * BN + wn * 64 + ni * 8 + 2 * q;   // even -> float2-aligned
        const float2 yt2 = *(const float2*)&g_bt[cg];
        const float2 sb2 = *(const float2*)&g_sb[cg];
        #pragma unroll
        for (int mi = 0; mi < 2; ++mi) {
            #pragma unroll
            for (int h = 0; h < 2; ++h) {
                const int i = mi * 2 + h;
                float va = fmaf(-(float)acc[mi][ni][h * 2 + 0], sb2.x, xs[i] * yt2.x);
                float vb = fmaf(-(float)acc[mi][ni][h * 2 + 1], sb2.y, xs[i] * yt2.y);
                const bool pa = (cg == tg[i]);
                const bool pb = (cg + 1 == tg[i]);
                vp[i] = pa ? va : vp[i];
                va    = pa ? FINF : va;
                vp[i] = pb ? vb : vp[i];
                vb    = pb ? FINF : vb;
                float mxa = fmaxf(m1[i], va);
                m1[i] = fminf(m1[i], va);
                m2[i] = fminf(m2[i], mxa);
                float mxb = fmaxf(m1[i], vb);
                m1[i] = fminf(m1[i], vb);
                m2[i] = fminf(m2[i], mxb);
            }
        }
    }

    // Quad merge (q lanes share rows; same row -> same sa -> order preserved)
    #pragma unroll
    for (int i = 0; i < 4; ++i) {
        #pragma unroll
        for (int off = 1; off <= 2; off <<= 1) {
            float o1 = __shfl_xor_sync(0xffffffffu, m1[i], off);
            float o2 = __shfl_xor_sync(0xffffffffu, m2[i], off);
            float op = __shfl_xor_sync(0xffffffffu, vp[i], off);
            float n1 = fminf(m1[i], o1);
            float n2 = fminf(fmaxf(m1[i], o1), fminf(m2[i], o2));
            m1[i] = n1; m2[i] = n2;
            vp[i] = fminf(vp[i], op);
        }
    }

    // wn merge via smem (reuses stage 0 region — protected by mainloop barrier).
    float* r1 = (float*)smem;
    float* r2 = r1 + 2 * BM;
    float* rp = r2 + 2 * BM;
    if (q == 0) {
        #pragma unroll
        for (int i = 0; i < 4; ++i) {
            const int rl = wm * 32 + (i >> 1) * 16 + (i & 1) * 8 + g;
            r1[wn * BM + rl] = m1[i];
            r2[wn * BM + rl] = m2[i];
            rp[wn * BM + rl] = vp[i];
        }
    }
    __syncthreads();
    if (tid < BM) {
        const float saw = g_sa[mt * BM + tid];    // restore per-row scale
        const float a1 = r1[tid], b1 = r1[BM + tid];
        const float a2 = r2[tid], b2 = r2[BM + tid];
        const float n1 = fminf(a1, b1);
        const float n2 = fminf(fmaxf(a1, b1), fminf(a2, b2));
        const int gi = ct * M_ROWS + mt * BM + tid;
        g_p1[gi] = n1 * saw;
        g_p2[gi] = n2 * saw;
        g_pp[gi] = fminf(rp[tid], rp[BM + tid]) * saw;
    }
}

// ---------------------------------------------------------------------------
// Merge partials across 32 ct-tiles + per-sample loss.
// ---------------------------------------------------------------------------
__global__ void merge_loss(const float* __restrict__ curv_log, float* __restrict__ out) {
    const int r = blockIdx.x * 256 + threadIdx.x;
    float a1 = g_p1[r], a2 = g_p2[r], ap = g_pp[r];
    #pragma unroll 4
    for (int ct = 1; ct < NCT; ++ct) {
        const float b1 = g_p1[ct * M_ROWS + r];
        const float b2 = g_p2[ct * M_ROWS + r];
        const float n1 = fminf(a1, b1);
        a2 = fminf(fmaxf(a1, b1), fminf(a2, b2));
        a1 = n1;
        ap = fminf(ap, g_pp[ct * M_ROWS + r]);
    }
    const float curv = expf(curv_log[0]);
    const float sc = sqrtf(curv);
    const float dp = acoshf(fmaxf(curv * ap, 1.0f)) / sc;
    const float d1 = acoshf(fmaxf(curv * a1, 1.0f)) / sc;
    const float d2 = acoshf(fmaxf(curv * a2, 1.0f)) / sc;
    const float s0 = -dp, s1 = -d1, s2 = -d2;
    const float mx = fmaxf(s0, fmaxf(s1, s2));
    out[r] = mx + logf(expf(s0 - mx) + expf(s1 - mx) + expf(s2 - mx)) - s0;
}

extern "C" void kernel_launch(void* const* d_in, const int* in_sizes, int n_in,
                              void* d_out, int out_size) {
    const float* text     = (const float*)d_in[0];
    const float* label    = (const float*)d_in[1];
    const int*   tgt      = (const int*)d_in[2];
    const float* curv_log = (const float*)d_in[3];
    const float* ta_log   = (const float*)d_in[4];
    const float* la_log   = (const float*)d_in[5];
    float* out = (float*)d_out;

    cudaFuncSetAttribute(clloss_main, cudaFuncAttributeMaxDynamicSharedMemorySize, SMEM_BYTES);

    prep_kernel<<<(M_ROWS + C_COLS) / 8, 256>>>(text, label, curv_log, ta_log, la_log);
    clloss_main<<<NMT * NCT, NTH, SMEM_BYTES>>>(tgt);
    merge_loss<<<M_ROWS / 256, 256>>>(curv_log, out);
}